// round 8
// baseline (speedup 1.0000x reference)
#include <cuda_runtime.h>
#include <cuda_bf16.h>

// Shapes fixed by setup_inputs: B=32, P=32, S=512
static constexpr int B   = 32;
static constexpr int P   = 32;
static constexpr int S   = 512;
static constexpr int PS  = P * S;                    // 16384
static constexpr size_t NOUT = (size_t)B * P * PS;   // 16777216 per output tensor

// Single fused kernel, affine-composed form:
//   p_loc = Mf * c + df   (9 FMA/element), pen = relu(s_p - |p_loc|), out = |pen|^2 * gate
// Block = (b, p, chunk of 1024 j). The 1024-j span covers exactly 2 owners
// (S=512); 2 threads build per-owner {Mf[9], df[3], wv, gate} into smem.
__global__ void __launch_bounds__(256) fused_kernel(const float* __restrict__ shape,
                                                    const float* __restrict__ trans,
                                                    const float* __restrict__ quat,
                                                    const float* __restrict__ iou,
                                                    const float* __restrict__ coef,
                                                    float* __restrict__ tsdfOut,
                                                    float* __restrict__ weight,
                                                    float* __restrict__ tsdfGT) {
    int blk = blockIdx.x;            // 0..16383
    int bp  = blk >> 4;              // b*P + p
    int chunk = blk & 15;
    int b = bp >> 5;
    int p = bp & 31;
    int tid = threadIdx.x;

    __shared__ float sm[2][14];      // per owner: Mf[0..8], df[9..11], wv[12], gate[13]

    if (tid < 2) {
        int o  = 2 * chunk + tid;
        int bo = (b << 5) + o;

        // owner quat -> rotation matrix A = R(q_o)
        float4 qo = *reinterpret_cast<const float4*>(&quat[bo * 4]);
        float ni = rsqrtf(qo.x*qo.x + qo.y*qo.y + qo.z*qo.z + qo.w*qo.w);
        float w = qo.x*ni, x = qo.y*ni, y = qo.z*ni, z = qo.w*ni;
        float a00 = 1.0f - 2.0f*(y*y + z*z), a01 = 2.0f*(x*y - w*z), a02 = 2.0f*(x*z + w*y);
        float a10 = 2.0f*(x*y + w*z), a11 = 1.0f - 2.0f*(x*x + z*z), a12 = 2.0f*(y*z - w*x);
        float a20 = 2.0f*(x*z - w*y), a21 = 2.0f*(y*z + w*x), a22 = 1.0f - 2.0f*(x*x + y*y);

        // self quat, conjugated -> Bm = R(conj q_p) = R(q_p)^T
        float4 qp = *reinterpret_cast<const float4*>(&quat[bp * 4]);
        float pi2 = rsqrtf(qp.x*qp.x + qp.y*qp.y + qp.z*qp.z + qp.w*qp.w);
        float pw = qp.x*pi2, px = -qp.y*pi2, py = -qp.z*pi2, pz = -qp.w*pi2;
        float b00 = 1.0f - 2.0f*(py*py + pz*pz), b01 = 2.0f*(px*py - pw*pz), b02 = 2.0f*(px*pz + pw*py);
        float b10 = 2.0f*(px*py + pw*pz), b11 = 1.0f - 2.0f*(px*px + pz*pz), b12 = 2.0f*(py*pz - pw*px);
        float b20 = 2.0f*(px*pz - pw*py), b21 = 2.0f*(py*pz + pw*px), b22 = 1.0f - 2.0f*(px*px + py*py);

        // M = Bm * A
        float m00 = b00*a00 + b01*a10 + b02*a20;
        float m01 = b00*a01 + b01*a11 + b02*a21;
        float m02 = b00*a02 + b01*a12 + b02*a22;
        float m10 = b10*a00 + b11*a10 + b12*a20;
        float m11 = b10*a01 + b11*a11 + b12*a21;
        float m12 = b10*a02 + b11*a12 + b12*a22;
        float m20 = b20*a00 + b21*a10 + b22*a20;
        float m21 = b20*a01 + b21*a11 + b22*a21;
        float m22 = b20*a02 + b21*a12 + b22*a22;

        // d = Bm * (t_o - t_p)
        float dx = trans[bo*3+0] - trans[bp*3+0];
        float dy = trans[bo*3+1] - trans[bp*3+1];
        float dz = trans[bo*3+2] - trans[bp*3+2];
        float d0 = b00*dx + b01*dy + b02*dz;
        float d1 = b10*dx + b11*dy + b12*dz;
        float d2 = b20*dx + b21*dy + b22*dz;

        // fold owner shape + (2c-1): Mf = 2*M*diag(s_o); df = d - M*s_o
        float osx = shape[bo*3+0], osy = shape[bo*3+1], osz = shape[bo*3+2];
        sm[tid][0] = 2.0f*m00*osx; sm[tid][1] = 2.0f*m01*osy; sm[tid][2] = 2.0f*m02*osz;
        sm[tid][3] = 2.0f*m10*osx; sm[tid][4] = 2.0f*m11*osy; sm[tid][5] = 2.0f*m12*osz;
        sm[tid][6] = 2.0f*m20*osx; sm[tid][7] = 2.0f*m21*osy; sm[tid][8] = 2.0f*m22*osz;
        sm[tid][9]  = d0 - (m00*osx + m01*osy + m02*osz);
        sm[tid][10] = d1 - (m10*osx + m11*osy + m12*osz);
        sm[tid][11] = d2 - (m20*osx + m21*osy + m22*osz);
        sm[tid][12] = osx * osy * osz * iou[bo];            // weight value
        sm[tid][13] = (o != p) ? iou[bp] : 0.0f;            // gate
    }
    __syncthreads();

    int j0 = chunk * 1024 + tid * 4;          // 4 consecutive j, one owner per thread
    const float* Sp = sm[(tid >= 128) ? 1 : 0];   // warp-uniform -> LDS broadcast
    float m00 = Sp[0], m01 = Sp[1], m02 = Sp[2];
    float m10 = Sp[3], m11 = Sp[4], m12 = Sp[5];
    float m20 = Sp[6], m21 = Sp[7], m22 = Sp[8];
    float d0 = Sp[9], d1 = Sp[10], d2 = Sp[11];
    float wv = Sp[12], gate = Sp[13];
    float sx = shape[bp*3+0], sy = shape[bp*3+1], sz = shape[bp*3+2];

    // coef: 4 j * 3 comps = 12 consecutive floats, 16B aligned
    const float* cptr = &coef[((size_t)b * PS + j0) * 3];
    float4 c0 = *reinterpret_cast<const float4*>(cptr + 0);
    float4 c1 = *reinterpret_cast<const float4*>(cptr + 4);
    float4 c2 = *reinterpret_cast<const float4*>(cptr + 8);
    float cc[12] = {c0.x, c0.y, c0.z, c0.w, c1.x, c1.y, c1.z, c1.w,
                    c2.x, c2.y, c2.z, c2.w};

    float4 outv;
    float* os = &outv.x;
#pragma unroll
    for (int k = 0; k < 4; k++) {
        float cx = cc[k*3+0], cy = cc[k*3+1], cz = cc[k*3+2];
        float lx = fmaf(m00, cx, fmaf(m01, cy, fmaf(m02, cz, d0)));
        float ly = fmaf(m10, cx, fmaf(m11, cy, fmaf(m12, cz, d1)));
        float lz = fmaf(m20, cx, fmaf(m21, cy, fmaf(m22, cz, d2)));
        float ex = fmaxf(sx - fabsf(lx), 0.0f);
        float ey = fmaxf(sy - fabsf(ly), 0.0f);
        float ez = fmaxf(sz - fabsf(lz), 0.0f);
        os[k] = fmaf(ez, ez, fmaf(ey, ey, ex * ex)) * gate;
    }

    size_t base = (size_t)bp * PS + j0;
    *reinterpret_cast<float4*>(&tsdfOut[base]) = outv;
    *reinterpret_cast<float4*>(&weight[base])  = make_float4(wv, wv, wv, wv);
    *reinterpret_cast<float4*>(&tsdfGT[base])  = make_float4(0.f, 0.f, 0.f, 0.f);
}

extern "C" void kernel_launch(void* const* d_in, const int* in_sizes, int n_in,
                              void* d_out, int out_size) {
    const float* shape = (const float*)d_in[0];
    const float* trans = (const float*)d_in[1];
    const float* quat  = (const float*)d_in[2];
    const float* iou   = (const float*)d_in[3];
    const float* coef  = (const float*)d_in[4];
    float* out = (float*)d_out;

    fused_kernel<<<B * P * 16, 256>>>(shape, trans, quat, iou, coef,
                                      out, out + NOUT, out + 2 * NOUT);
}

// round 10
// speedup vs baseline: 1.2130x; 1.2130x over previous
#include <cuda_runtime.h>
#include <cuda_bf16.h>

// Shapes fixed by setup_inputs: B=32, P=32, S=512
static constexpr int B   = 32;
static constexpr int P   = 32;
static constexpr int S   = 512;
static constexpr int PS  = P * S;                    // 16384
static constexpr size_t NOUT = (size_t)B * P * PS;   // 16777216 per output tensor

// One block per (b,p): 512 threads, 8 iterations x 4 j/thread = 16384 j.
// Warp 0 builds all 32 owners' affine params {Mf[9], df[3], wv, gate} once;
// main loop is 9 FMA + relu-pen per element, fully store-bound.
__global__ void __launch_bounds__(512) fused_kernel(const float* __restrict__ shape,
                                                    const float* __restrict__ trans,
                                                    const float* __restrict__ quat,
                                                    const float* __restrict__ iou,
                                                    const float* __restrict__ coef,
                                                    float* __restrict__ tsdfOut,
                                                    float* __restrict__ weight,
                                                    float* __restrict__ tsdfGT) {
    int bp = blockIdx.x;             // b*P + p
    int b = bp >> 5;
    int p = bp & 31;
    int tid = threadIdx.x;

    __shared__ float sm[32][14];     // per owner: Mf[0..8], df[9..11], wv[12], gate[13]

    if (tid < 32) {
        int o  = tid;
        int bo = (b << 5) + o;

        // owner quat -> rotation matrix A = R(q_o)
        float4 qo = *reinterpret_cast<const float4*>(&quat[bo * 4]);
        float ni = rsqrtf(qo.x*qo.x + qo.y*qo.y + qo.z*qo.z + qo.w*qo.w);
        float w = qo.x*ni, x = qo.y*ni, y = qo.z*ni, z = qo.w*ni;
        float a00 = 1.0f - 2.0f*(y*y + z*z), a01 = 2.0f*(x*y - w*z), a02 = 2.0f*(x*z + w*y);
        float a10 = 2.0f*(x*y + w*z), a11 = 1.0f - 2.0f*(x*x + z*z), a12 = 2.0f*(y*z - w*x);
        float a20 = 2.0f*(x*z - w*y), a21 = 2.0f*(y*z + w*x), a22 = 1.0f - 2.0f*(x*x + y*y);

        // self quat, conjugated -> Bm = R(conj q_p) = R(q_p)^T
        float4 qp = *reinterpret_cast<const float4*>(&quat[bp * 4]);
        float pi2 = rsqrtf(qp.x*qp.x + qp.y*qp.y + qp.z*qp.z + qp.w*qp.w);
        float pw = qp.x*pi2, px = -qp.y*pi2, py = -qp.z*pi2, pz = -qp.w*pi2;
        float b00 = 1.0f - 2.0f*(py*py + pz*pz), b01 = 2.0f*(px*py - pw*pz), b02 = 2.0f*(px*pz + pw*py);
        float b10 = 2.0f*(px*py + pw*pz), b11 = 1.0f - 2.0f*(px*px + pz*pz), b12 = 2.0f*(py*pz - pw*px);
        float b20 = 2.0f*(px*pz - pw*py), b21 = 2.0f*(py*pz + pw*px), b22 = 1.0f - 2.0f*(px*px + py*py);

        // M = Bm * A
        float m00 = b00*a00 + b01*a10 + b02*a20;
        float m01 = b00*a01 + b01*a11 + b02*a21;
        float m02 = b00*a02 + b01*a12 + b02*a22;
        float m10 = b10*a00 + b11*a10 + b12*a20;
        float m11 = b10*a01 + b11*a11 + b12*a21;
        float m12 = b10*a02 + b11*a12 + b12*a22;
        float m20 = b20*a00 + b21*a10 + b22*a20;
        float m21 = b20*a01 + b21*a11 + b22*a21;
        float m22 = b20*a02 + b21*a12 + b22*a22;

        // d = Bm * (t_o - t_p)
        float dx = trans[bo*3+0] - trans[bp*3+0];
        float dy = trans[bo*3+1] - trans[bp*3+1];
        float dz = trans[bo*3+2] - trans[bp*3+2];
        float d0 = b00*dx + b01*dy + b02*dz;
        float d1 = b10*dx + b11*dy + b12*dz;
        float d2 = b20*dx + b21*dy + b22*dz;

        // fold owner shape + (2c-1): Mf = 2*M*diag(s_o); df = d - M*s_o
        float osx = shape[bo*3+0], osy = shape[bo*3+1], osz = shape[bo*3+2];
        sm[o][0] = 2.0f*m00*osx; sm[o][1] = 2.0f*m01*osy; sm[o][2] = 2.0f*m02*osz;
        sm[o][3] = 2.0f*m10*osx; sm[o][4] = 2.0f*m11*osy; sm[o][5] = 2.0f*m12*osz;
        sm[o][6] = 2.0f*m20*osx; sm[o][7] = 2.0f*m21*osy; sm[o][8] = 2.0f*m22*osz;
        sm[o][9]  = d0 - (m00*osx + m01*osy + m02*osz);
        sm[o][10] = d1 - (m10*osx + m11*osy + m12*osz);
        sm[o][11] = d2 - (m20*osx + m21*osy + m22*osz);
        sm[o][12] = osx * osy * osz * iou[bo];           // weight value
        sm[o][13] = (o != p) ? iou[bp] : 0.0f;           // gate
    }
    __syncthreads();

    float sx = shape[bp*3+0], sy = shape[bp*3+1], sz = shape[bp*3+2];
    size_t row = (size_t)bp * PS;
    size_t brow = (size_t)b * PS;

#pragma unroll
    for (int it = 0; it < 8; it++) {
        int j0 = it * 2048 + tid * 4;         // warp spans 128 j inside one 512-j owner block
        int o  = j0 >> 9;
        const float* Sp = sm[o];              // warp-uniform -> LDS broadcast
        float m00 = Sp[0], m01 = Sp[1], m02 = Sp[2];
        float m10 = Sp[3], m11 = Sp[4], m12 = Sp[5];
        float m20 = Sp[6], m21 = Sp[7], m22 = Sp[8];
        float d0 = Sp[9], d1 = Sp[10], d2 = Sp[11];
        float wv = Sp[12], gate = Sp[13];

        const float* cptr = &coef[(brow + j0) * 3];
        float4 c0 = *reinterpret_cast<const float4*>(cptr + 0);
        float4 c1 = *reinterpret_cast<const float4*>(cptr + 4);
        float4 c2 = *reinterpret_cast<const float4*>(cptr + 8);
        float cc[12] = {c0.x, c0.y, c0.z, c0.w, c1.x, c1.y, c1.z, c1.w,
                        c2.x, c2.y, c2.z, c2.w};

        float4 outv;
        float* os = &outv.x;
#pragma unroll
        for (int k = 0; k < 4; k++) {
            float cx = cc[k*3+0], cy = cc[k*3+1], cz = cc[k*3+2];
            float lx = fmaf(m00, cx, fmaf(m01, cy, fmaf(m02, cz, d0)));
            float ly = fmaf(m10, cx, fmaf(m11, cy, fmaf(m12, cz, d1)));
            float lz = fmaf(m20, cx, fmaf(m21, cy, fmaf(m22, cz, d2)));
            float ex = fmaxf(sx - fabsf(lx), 0.0f);
            float ey = fmaxf(sy - fabsf(ly), 0.0f);
            float ez = fmaxf(sz - fabsf(lz), 0.0f);
            os[k] = fmaf(ez, ez, fmaf(ey, ey, ex * ex)) * gate;
        }

        size_t base = row + j0;
        *reinterpret_cast<float4*>(&tsdfOut[base]) = outv;
        *reinterpret_cast<float4*>(&weight[base])  = make_float4(wv, wv, wv, wv);
        *reinterpret_cast<float4*>(&tsdfGT[base])  = make_float4(0.f, 0.f, 0.f, 0.f);
    }
}

extern "C" void kernel_launch(void* const* d_in, const int* in_sizes, int n_in,
                              void* d_out, int out_size) {
    const float* shape = (const float*)d_in[0];
    const float* trans = (const float*)d_in[1];
    const float* quat  = (const float*)d_in[2];
    const float* iou   = (const float*)d_in[3];
    const float* coef  = (const float*)d_in[4];
    float* out = (float*)d_out;

    fused_kernel<<<B * P, 512>>>(shape, trans, quat, iou, coef,
                                 out, out + NOUT, out + 2 * NOUT);
}

// round 11
// speedup vs baseline: 1.2526x; 1.0326x over previous
#include <cuda_runtime.h>
#include <cuda_bf16.h>

// Shapes fixed by setup_inputs: B=32, P=32, S=512
static constexpr int B   = 32;
static constexpr int P   = 32;
static constexpr int S   = 512;
static constexpr int PS  = P * S;                    // 16384
static constexpr size_t NOUT = (size_t)B * P * PS;   // 16777216 per output tensor

// One block per (b,p): 512 threads, 8 iterations x 4 j/thread = 16384 j.
// Warp 0 builds all 32 owners' affine params once. __launch_bounds__(512,3)
// caps regs at 42 -> 48 warps/SM so the 3-stream store traffic stays covered.
__global__ void __launch_bounds__(512, 3) fused_kernel(const float* __restrict__ shape,
                                                       const float* __restrict__ trans,
                                                       const float* __restrict__ quat,
                                                       const float* __restrict__ iou,
                                                       const float* __restrict__ coef,
                                                       float* __restrict__ tsdfOut,
                                                       float* __restrict__ weight,
                                                       float* __restrict__ tsdfGT) {
    int bp = blockIdx.x;             // b*P + p
    int b = bp >> 5;
    int p = bp & 31;
    int tid = threadIdx.x;

    __shared__ float sm[32][14];     // per owner: Mf[0..8], df[9..11], wv[12], gate[13]

    if (tid < 32) {
        int o  = tid;
        int bo = (b << 5) + o;

        // owner quat -> rotation matrix A = R(q_o)
        float4 qo = *reinterpret_cast<const float4*>(&quat[bo * 4]);
        float ni = rsqrtf(qo.x*qo.x + qo.y*qo.y + qo.z*qo.z + qo.w*qo.w);
        float w = qo.x*ni, x = qo.y*ni, y = qo.z*ni, z = qo.w*ni;
        float a00 = 1.0f - 2.0f*(y*y + z*z), a01 = 2.0f*(x*y - w*z), a02 = 2.0f*(x*z + w*y);
        float a10 = 2.0f*(x*y + w*z), a11 = 1.0f - 2.0f*(x*x + z*z), a12 = 2.0f*(y*z - w*x);
        float a20 = 2.0f*(x*z - w*y), a21 = 2.0f*(y*z + w*x), a22 = 1.0f - 2.0f*(x*x + y*y);

        // self quat, conjugated -> Bm = R(conj q_p) = R(q_p)^T
        float4 qp = *reinterpret_cast<const float4*>(&quat[bp * 4]);
        float pi2 = rsqrtf(qp.x*qp.x + qp.y*qp.y + qp.z*qp.z + qp.w*qp.w);
        float pw = qp.x*pi2, px = -qp.y*pi2, py = -qp.z*pi2, pz = -qp.w*pi2;
        float b00 = 1.0f - 2.0f*(py*py + pz*pz), b01 = 2.0f*(px*py - pw*pz), b02 = 2.0f*(px*pz + pw*py);
        float b10 = 2.0f*(px*py + pw*pz), b11 = 1.0f - 2.0f*(px*px + pz*pz), b12 = 2.0f*(py*pz - pw*px);
        float b20 = 2.0f*(px*pz - pw*py), b21 = 2.0f*(py*pz + pw*px), b22 = 1.0f - 2.0f*(px*px + py*py);

        // M = Bm * A
        float m00 = b00*a00 + b01*a10 + b02*a20;
        float m01 = b00*a01 + b01*a11 + b02*a21;
        float m02 = b00*a02 + b01*a12 + b02*a22;
        float m10 = b10*a00 + b11*a10 + b12*a20;
        float m11 = b10*a01 + b11*a11 + b12*a21;
        float m12 = b10*a02 + b11*a12 + b12*a22;
        float m20 = b20*a00 + b21*a10 + b22*a20;
        float m21 = b20*a01 + b21*a11 + b22*a21;
        float m22 = b20*a02 + b21*a12 + b22*a22;

        // d = Bm * (t_o - t_p)
        float dx = trans[bo*3+0] - trans[bp*3+0];
        float dy = trans[bo*3+1] - trans[bp*3+1];
        float dz = trans[bo*3+2] - trans[bp*3+2];
        float d0 = b00*dx + b01*dy + b02*dz;
        float d1 = b10*dx + b11*dy + b12*dz;
        float d2 = b20*dx + b21*dy + b22*dz;

        // fold owner shape + (2c-1): Mf = 2*M*diag(s_o); df = d - M*s_o
        float osx = shape[bo*3+0], osy = shape[bo*3+1], osz = shape[bo*3+2];
        sm[o][0] = 2.0f*m00*osx; sm[o][1] = 2.0f*m01*osy; sm[o][2] = 2.0f*m02*osz;
        sm[o][3] = 2.0f*m10*osx; sm[o][4] = 2.0f*m11*osy; sm[o][5] = 2.0f*m12*osz;
        sm[o][6] = 2.0f*m20*osx; sm[o][7] = 2.0f*m21*osy; sm[o][8] = 2.0f*m22*osz;
        sm[o][9]  = d0 - (m00*osx + m01*osy + m02*osz);
        sm[o][10] = d1 - (m10*osx + m11*osy + m12*osz);
        sm[o][11] = d2 - (m20*osx + m21*osy + m22*osz);
        sm[o][12] = osx * osy * osz * iou[bo];           // weight value
        sm[o][13] = (o != p) ? iou[bp] : 0.0f;           // gate
    }
    __syncthreads();

    float sx = shape[bp*3+0], sy = shape[bp*3+1], sz = shape[bp*3+2];
    size_t row = (size_t)bp * PS;
    size_t brow = (size_t)b * PS;

#pragma unroll
    for (int it = 0; it < 8; it++) {
        int j0 = it * 2048 + tid * 4;         // warp spans 128 j inside one 512-j owner block
        int o  = j0 >> 9;
        const float* Sp = sm[o];              // warp-uniform -> LDS broadcast
        size_t base = row + j0;

        // Cheap stores first: short live ranges for wv/gate, early LSU issue.
        *reinterpret_cast<float4*>(&tsdfGT[base]) = make_float4(0.f, 0.f, 0.f, 0.f);
        float wv = Sp[12];
        *reinterpret_cast<float4*>(&weight[base]) = make_float4(wv, wv, wv, wv);
        float gate = Sp[13];

        const float* cptr = &coef[(brow + j0) * 3];
        float4 c0 = *reinterpret_cast<const float4*>(cptr + 0);
        float4 c1 = *reinterpret_cast<const float4*>(cptr + 4);
        float4 c2 = *reinterpret_cast<const float4*>(cptr + 8);

        float m00 = Sp[0], m01 = Sp[1], m02 = Sp[2];
        float m10 = Sp[3], m11 = Sp[4], m12 = Sp[5];
        float m20 = Sp[6], m21 = Sp[7], m22 = Sp[8];
        float d0 = Sp[9], d1 = Sp[10], d2 = Sp[11];

        float4 outv;
        {   // k=0: c0.x c0.y c0.z
            float lx = fmaf(m00, c0.x, fmaf(m01, c0.y, fmaf(m02, c0.z, d0)));
            float ly = fmaf(m10, c0.x, fmaf(m11, c0.y, fmaf(m12, c0.z, d1)));
            float lz = fmaf(m20, c0.x, fmaf(m21, c0.y, fmaf(m22, c0.z, d2)));
            float ex = fmaxf(sx - fabsf(lx), 0.0f);
            float ey = fmaxf(sy - fabsf(ly), 0.0f);
            float ez = fmaxf(sz - fabsf(lz), 0.0f);
            outv.x = fmaf(ez, ez, fmaf(ey, ey, ex * ex)) * gate;
        }
        {   // k=1: c0.w c1.x c1.y
            float lx = fmaf(m00, c0.w, fmaf(m01, c1.x, fmaf(m02, c1.y, d0)));
            float ly = fmaf(m10, c0.w, fmaf(m11, c1.x, fmaf(m12, c1.y, d1)));
            float lz = fmaf(m20, c0.w, fmaf(m21, c1.x, fmaf(m22, c1.y, d2)));
            float ex = fmaxf(sx - fabsf(lx), 0.0f);
            float ey = fmaxf(sy - fabsf(ly), 0.0f);
            float ez = fmaxf(sz - fabsf(lz), 0.0f);
            outv.y = fmaf(ez, ez, fmaf(ey, ey, ex * ex)) * gate;
        }
        {   // k=2: c1.z c1.w c2.x
            float lx = fmaf(m00, c1.z, fmaf(m01, c1.w, fmaf(m02, c2.x, d0)));
            float ly = fmaf(m10, c1.z, fmaf(m11, c1.w, fmaf(m12, c2.x, d1)));
            float lz = fmaf(m20, c1.z, fmaf(m21, c1.w, fmaf(m22, c2.x, d2)));
            float ex = fmaxf(sx - fabsf(lx), 0.0f);
            float ey = fmaxf(sy - fabsf(ly), 0.0f);
            float ez = fmaxf(sz - fabsf(lz), 0.0f);
            outv.z = fmaf(ez, ez, fmaf(ey, ey, ex * ex)) * gate;
        }
        {   // k=3: c2.y c2.z c2.w
            float lx = fmaf(m00, c2.y, fmaf(m01, c2.z, fmaf(m02, c2.w, d0)));
            float ly = fmaf(m10, c2.y, fmaf(m11, c2.z, fmaf(m12, c2.w, d1)));
            float lz = fmaf(m20, c2.y, fmaf(m21, c2.z, fmaf(m22, c2.w, d2)));
            float ex = fmaxf(sx - fabsf(lx), 0.0f);
            float ey = fmaxf(sy - fabsf(ly), 0.0f);
            float ez = fmaxf(sz - fabsf(lz), 0.0f);
            outv.w = fmaf(ez, ez, fmaf(ey, ey, ex * ex)) * gate;
        }

        *reinterpret_cast<float4*>(&tsdfOut[base]) = outv;
    }
}

extern "C" void kernel_launch(void* const* d_in, const int* in_sizes, int n_in,
                              void* d_out, int out_size) {
    const float* shape = (const float*)d_in[0];
    const float* trans = (const float*)d_in[1];
    const float* quat  = (const float*)d_in[2];
    const float* iou   = (const float*)d_in[3];
    const float* coef  = (const float*)d_in[4];
    float* out = (float*)d_out;

    fused_kernel<<<B * P, 512>>>(shape, trans, quat, iou, coef,
                                 out, out + NOUT, out + 2 * NOUT);
}